// round 17
// baseline (speedup 1.0000x reference)
#include <cuda_runtime.h>

#define D        256
#define H        16
#define RT1      256    // rows per block, kernel 1
#define TH1      256
#define CHUNK    16
#define NCH      16
#define XCFL     (RT1 * CHUNK)

#define RT2      256    // rows per block, kernel 2
#define TH2      256

typedef unsigned long long u64;

__device__ float h_scratch[8000000];   // 500000 * 16 floats = 32 MB

static __device__ __forceinline__ u64 pack2(float a, float b) {
    u64 r; asm("mov.b64 %0, {%1, %2};" : "=l"(r) : "f"(a), "f"(b)); return r;
}
static __device__ __forceinline__ void unpack2(u64 v, float& a, float& b) {
    asm("mov.b64 {%0, %1}, %2;" : "=f"(a), "=f"(b) : "l"(v));
}
static __device__ __forceinline__ u64 fma2(u64 a, u64 b, u64 c) {
    u64 d; asm("fma.rn.f32x2 %0, %1, %2, %3;" : "=l"(d) : "l"(a), "l"(b), "l"(c)); return d;
}
static __device__ __forceinline__ float ex2f(float x) {
    float r; asm("ex2.approx.f32 %0, %1;" : "=f"(r) : "f"(x)); return r;
}
static __device__ __forceinline__ float rcpf(float x) {
    float r; asm("rcp.approx.f32 %0, %1;" : "=f"(r) : "f"(x)); return r;
}
static __device__ __forceinline__ float sigmoid2(float s) {
    return rcpf(1.0f + ex2f(s * -2.8853900817779268f));
}
static __device__ __forceinline__ void cpa16(float* dst, const float* src) {
    unsigned s = (unsigned)__cvta_generic_to_shared(dst);
    asm volatile("cp.async.ca.shared.global [%0], [%1], 16;" :: "r"(s), "l"(src) : "memory");
}
static __device__ __forceinline__ void cpa_commit() {
    asm volatile("cp.async.commit_group;" ::: "memory");
}

// ============ Kernel 1: h = relu(x @ W1) -> h_scratch =======================
// Shared (floats): W1s [0,4096) | xcA [4096,8192) | xcB [8192,12288). 48 KB.
__global__ __launch_bounds__(TH1, 4)
void fb_pass1(const float* __restrict__ x, const float* __restrict__ W1, int n)
{
    extern __shared__ float smem[];
    float* W1s = smem;
    float* xcA = smem + 4096;
    float* xcB = smem + 8192;

    const int t     = threadIdx.x;
    const int row0  = blockIdx.x * RT1;
    const int nrows = min(RT1, n - row0);

    #pragma unroll
    for (int i = 0; i < 16; i++) W1s[t + i * TH1] = W1[t + i * TH1];

    // prologue: prefetch chunks 0 (A) and 1 (B)
    #pragma unroll
    for (int c = 0; c < 2; c++) {
        float* buf = c ? xcB : xcA;
        #pragma unroll
        for (int it = 0; it < 4; it++) {
            int idx = t + it * TH1;
            int rr = idx >> 2, q = idx & 3;
            if (rr < nrows)
                cpa16(buf + rr * CHUNK + 4 * (q ^ ((rr >> 1) & 3)),
                      x + (long long)(row0 + rr) * D + c * CHUNK + 4 * q);
        }
        cpa_commit();
    }

    const int r   = t;
    const int qs1 = (r >> 1) & 3;
    u64 acc[8];
    #pragma unroll
    for (int i = 0; i < 8; i++) acc[i] = 0ULL;

    for (int c = 0; c < NCH; c++) {
        if (c < NCH - 1) asm volatile("cp.async.wait_group 1;" ::: "memory");
        else             asm volatile("cp.async.wait_group 0;" ::: "memory");
        __syncthreads();

        const float* myrow = (c & 1 ? xcB : xcA) + r * CHUNK;
        const float* wbase = W1s + c * CHUNK * H;
        #pragma unroll
        for (int q = 0; q < 4; q++) {
            float4 xv = *reinterpret_cast<const float4*>(myrow + 4 * (q ^ qs1));
            #pragma unroll
            for (int i = 0; i < 4; i++) {
                float xs = (i == 0) ? xv.x : (i == 1) ? xv.y : (i == 2) ? xv.z : xv.w;
                u64 xx = pack2(xs, xs);
                const ulonglong2* wq =
                    reinterpret_cast<const ulonglong2*>(wbase + (4 * q + i) * H);
                ulonglong2 wa = wq[0], wb = wq[1];
                acc[0] = fma2(xx, wa.x, acc[0]);
                acc[1] = fma2(xx, wa.y, acc[1]);
                acc[2] = fma2(xx, wb.x, acc[2]);
                acc[3] = fma2(xx, wb.y, acc[3]);
                ulonglong2 wc = wq[2], wd = wq[3];
                acc[4] = fma2(xx, wc.x, acc[4]);
                acc[5] = fma2(xx, wc.y, acc[5]);
                acc[6] = fma2(xx, wd.x, acc[6]);
                acc[7] = fma2(xx, wd.y, acc[7]);
            }
        }
        __syncthreads();

        if (c + 2 < NCH) {
            float* buf = (c & 1) ? xcB : xcA;
            #pragma unroll
            for (int it = 0; it < 4; it++) {
                int idx = t + it * TH1;
                int rr = idx >> 2, q = idx & 3;
                if (rr < nrows)
                    cpa16(buf + rr * CHUNK + 4 * (q ^ ((rr >> 1) & 3)),
                          x + (long long)(row0 + rr) * D + (c + 2) * CHUNK + 4 * q);
            }
            cpa_commit();
        }
    }

    // ReLU + store h row to scratch (contiguous 64 B per thread)
    if (r < nrows) {
        float4* hd = reinterpret_cast<float4*>(h_scratch + (long long)(row0 + r) * H);
        #pragma unroll
        for (int q = 0; q < 4; q++) {
            float a0, a1, b0, b1;
            unpack2(acc[2 * q + 0], a0, a1);
            unpack2(acc[2 * q + 1], b0, b1);
            hd[q] = make_float4(fmaxf(a0, 0.f), fmaxf(a1, 0.f),
                                fmaxf(b0, 0.f), fmaxf(b1, 0.f));
        }
    }
}

// ============ Kernel 2: out = x * sigmoid(2 * h @ W2) =======================
// Warp layout (R11-proven): warps 0-3 -> rows 0-127, warps 4-7 -> rows 128-255.
// Each warp covers 2 k-columns (k0 = (w&3)*64+lane, k1 = k0+32).
__global__ __launch_bounds__(TH2, 5)
void fb_pass2(const float* __restrict__ x, const float* __restrict__ W2,
              float* __restrict__ out, int n)
{
    __shared__ __align__(16) float hs[RT2 * H];   // 16 KB

    const int t     = threadIdx.x;
    const int row0  = blockIdx.x * RT2;
    const int nrows = min(RT2, n - row0);

    // cooperative coalesced h-tile load
    const float4* hsrc = reinterpret_cast<const float4*>(h_scratch + (long long)row0 * H);
    for (int i = t; i < nrows * 4; i += TH2)
        reinterpret_cast<float4*>(hs)[i] = hsrc[i];
    __syncthreads();

    const int w = t >> 5, lane = t & 31;
    const int rbase = (w >> 2) * 128;       // half-tile of rows per warp group
    const int kq = w & 3;
    const int k0 = kq * 64 + lane;
    const int k1 = k0 + 32;

    u64 w2a[8], w2b[8];                     // W2 columns k0, k1 (j-pairs)
    #pragma unroll
    for (int j = 0; j < 8; j++) {
        w2a[j] = pack2(W2[(2 * j) * D + k0], W2[(2 * j + 1) * D + k0]);
        w2b[j] = pack2(W2[(2 * j) * D + k1], W2[(2 * j + 1) * D + k1]);
    }

    const int rend = max(0, min(128, nrows - rbase));
    const long long gbase = (long long)(row0 + rbase) * D;

    float nx0 = 0.f, nx1 = 0.f;
    if (rend > 0) { nx0 = x[gbase + k0]; nx1 = x[gbase + k1]; }

    #pragma unroll 4
    for (int ri = 0; ri < rend; ri++) {
        float xv0 = nx0, xv1 = nx1;
        if (ri + 1 < rend) {
            nx0 = x[gbase + (long long)(ri + 1) * D + k0];
            nx1 = x[gbase + (long long)(ri + 1) * D + k1];
        }
        const float* hr = hs + (rbase + ri) * H;   // uniform -> broadcast LDS
        u64 sa = 0ULL, sb = 0ULL;
        #pragma unroll
        for (int q = 0; q < 4; q++) {
            ulonglong2 hq = *reinterpret_cast<const ulonglong2*>(hr + 4 * q);
            sa = fma2(hq.x, w2a[2 * q + 0], sa);
            sb = fma2(hq.x, w2b[2 * q + 0], sb);
            sa = fma2(hq.y, w2a[2 * q + 1], sa);
            sb = fma2(hq.y, w2b[2 * q + 1], sb);
        }
        float a0, a1, b0, b1;
        unpack2(sa, a0, a1);
        float s0 = a0 + a1;
        unpack2(sb, b0, b1);
        float s1 = b0 + b1;

        long long g = gbase + (long long)ri * D;
        out[g + k0] = xv0 * sigmoid2(s0);
        out[g + k1] = xv1 * sigmoid2(s1);
    }
}

extern "C" void kernel_launch(void* const* d_in, const int* in_sizes, int n_in,
                              void* d_out, int out_size) {
    const float* x  = (const float*)d_in[0];
    const float* W1 = (const float*)d_in[1];
    const float* W2 = (const float*)d_in[2];
    float* out = (float*)d_out;
    int n = in_sizes[0] / D;

    int smem1 = (4096 + 2 * XCFL) * (int)sizeof(float);   // 48 KB
    cudaFuncSetAttribute(fb_pass1, cudaFuncAttributeMaxDynamicSharedMemorySize, smem1);

    int grid1 = (n + RT1 - 1) / RT1;
    int grid2 = (n + RT2 - 1) / RT2;
    fb_pass1<<<grid1, TH1, smem1>>>(x, W1, n);
    fb_pass2<<<grid2, TH2>>>(x, W2, out, n);
}